// round 5
// baseline (speedup 1.0000x reference)
#include <cuda_runtime.h>
#include <cuda_bf16.h>

typedef unsigned long long u64;

#define T_N 4096

// ---- shared layout (float word offsets) ----
#define SWI   0        // Wi1: [3 dots][64 j][4 kc][4] = 3072
#define SWP   3072     // Wp:  [64 j][4 kc][4] = 1024
#define SBIAS 4096     // 8 rows x 64: bi1r,bi1z,bi1n,bhn1,bi2r,bi2z,bi2n,bp
#define H1B   4608     // [2 slot][2 b][64 phys] = 256
#define H2B   4864     // 256
#define O1B   5120     // ring [4][2][64 phys] = 512
#define XBUF  5632     // [4 slot][2 b][16] = 128
#define XI2B  5760     // [2 slot][2 b][192] = 768
#define XPB   6528     // [2 slot][2 b][64] = 256
#define SCB   6784     // [2 slot][2 b][8 warp] = 32
#define SATT  6816     // [2][64] = 128
#define SM1   6944     // 256
#define SM2   7200     // 128
#define SM3   7328     // 64
#define STOT  7392

__device__ __forceinline__ void ffma2(u64 &d, u64 a, u64 b) {
    asm("fma.rn.f32x2 %0, %1, %2, %0;" : "+l"(d) : "l"(a), "l"(b));
}
__device__ __forceinline__ u64 pack2(float lo, float hi) {
    u64 r; asm("mov.b64 %0, {%1, %2};" : "=l"(r) : "f"(lo), "f"(hi)); return r;
}
__device__ __forceinline__ float hsum2(u64 a) {
    float lo, hi;
    asm("mov.b64 {%0, %1}, %2;" : "=f"(lo), "=f"(hi) : "l"(a));
    return lo + hi;
}
__device__ __forceinline__ float sigf(float v)     { return __fdividef(1.f, 1.f + __expf(-v)); }
__device__ __forceinline__ float tanhfast(float v) { return 1.f - __fdividef(2.f, __expf(2.f * v) + 1.f); }

// 3 matrices x 2 batches, kc quarter (16 k) per thread, weights in registers.
// v points at [b0 64][b1 64] chunk-swizzled state; kc4 = kc*4 floats.
__device__ __forceinline__ void dot3x2(const u64 (&wa)[8], const u64 (&wb)[8], const u64 (&wc)[8],
                                       const float* v, int kc4,
                                       u64 &a0, u64 &a1, u64 &a2, u64 &c0, u64 &c1, u64 &c2)
{
#pragma unroll
    for (int m = 0; m < 4; ++m) {
        ulonglong2 x0 = *reinterpret_cast<const ulonglong2*>(v + m * 16 + kc4);
        ulonglong2 x1 = *reinterpret_cast<const ulonglong2*>(v + 64 + m * 16 + kc4);
        ffma2(a0, wa[2*m], x0.x); ffma2(a0, wa[2*m+1], x0.y);
        ffma2(a1, wb[2*m], x0.x); ffma2(a1, wb[2*m+1], x0.y);
        ffma2(a2, wc[2*m], x0.x); ffma2(a2, wc[2*m+1], x0.y);
        ffma2(c0, wa[2*m], x1.x); ffma2(c0, wa[2*m+1], x1.y);
        ffma2(c1, wb[2*m], x1.x); ffma2(c1, wb[2*m+1], x1.y);
        ffma2(c2, wc[2*m], x1.x); ffma2(c2, wc[2*m+1], x1.y);
    }
}

__global__ __launch_bounds__(768, 1)
void solar_fused(const float* __restrict__ x,
                 const float* __restrict__ Wi1,  const float* __restrict__ bi1,
                 const float* __restrict__ Whr1, const float* __restrict__ Whz1,
                 const float* __restrict__ Whn1, const float* __restrict__ bhn1,
                 const float* __restrict__ Wi2,  const float* __restrict__ bi2,
                 const float* __restrict__ Whr2, const float* __restrict__ Whz2,
                 const float* __restrict__ Whn2, const float* __restrict__ bhn2,
                 const float* __restrict__ Wp,   const float* __restrict__ bp,
                 const float* __restrict__ Wa,   const float* __restrict__ ba,
                 const float* __restrict__ W1,   const float* __restrict__ b1,
                 const float* __restrict__ W2,   const float* __restrict__ b2,
                 const float* __restrict__ W3,   const float* __restrict__ b3,
                 const float* __restrict__ W4,   const float* __restrict__ b4,
                 float* __restrict__ out)
{
    __shared__ __align__(16) float sm[STOT];

    const int tid  = threadIdx.x;
    const int grp  = tid >> 8;       // 0: L1-GRU, 1: Wi2+xproj, 2: L2-GRU+attn
    const int g    = tid & 255;
    const int j    = g >> 2;         // 0..63
    const int kc   = g & 3;          // k quarter
    const int kc4  = kc * 4;
    const int lane = tid & 31;
    const int wg   = g >> 5;         // warp index within group 0..7
    const int be   = kc >> 1;        // batch this lane finalizes
    const int be64 = be * 64;
    const bool wr_ = (kc & 1) == 0;  // writer lanes (kc 0,2)
    // physical (chunk-interleaved) index for scalar access to state vectors
    const int pj = ((j >> 2) & 3) * 16 + (j >> 4) * 4 + (j & 3);

    // ---------- register-resident weights ----------
    u64 wA[8], wB[8], wC[8];
    float cb0 = 0.f, cwa = 0.f, cba = 0.f;
    if (grp == 0) {
#pragma unroll
        for (int m = 0; m < 8; ++m) {
            int k = kc * 16 + 2 * m;
            wA[m] = pack2(Whr1[k*64 + j], Whr1[(k+1)*64 + j]);
            wB[m] = pack2(Whz1[k*64 + j], Whz1[(k+1)*64 + j]);
            wC[m] = pack2(Whn1[k*64 + j], Whn1[(k+1)*64 + j]);
        }
    } else if (grp == 1) {
#pragma unroll
        for (int m = 0; m < 8; ++m) {
            int k = kc * 16 + 2 * m;
            wA[m] = pack2(Wi2[k*192 + j],       Wi2[(k+1)*192 + j]);
            wB[m] = pack2(Wi2[k*192 + 64 + j],  Wi2[(k+1)*192 + 64 + j]);
            wC[m] = pack2(Wi2[k*192 + 128 + j], Wi2[(k+1)*192 + 128 + j]);
        }
    } else {
#pragma unroll
        for (int m = 0; m < 8; ++m) {
            int k = kc * 16 + 2 * m;
            wA[m] = pack2(Whr2[k*64 + j], Whr2[(k+1)*64 + j]);
            wB[m] = pack2(Whz2[k*64 + j], Whz2[(k+1)*64 + j]);
            wC[m] = pack2(Whn2[k*64 + j], Whn2[(k+1)*64 + j]);
        }
        cb0 = bhn2[j]; cwa = Wa[j]; cba = ba[0];
    }

    // ---------- shared setup ----------
    for (int idx = tid; idx < 3072; idx += 768) {        // Wi1 -> [dot][j][kc][4]
        int dot = idx >> 10, rem = idx & 1023;
        int jj = rem >> 4, kcf = rem & 15;
        int f = (kcf >> 2) * 4 + (kcf & 3);
        sm[SWI + idx] = Wi1[f * 192 + dot * 64 + jj];
    }
    for (int idx = tid; idx < 1024; idx += 768) {        // Wp -> [j][kc][4]
        int jj = idx >> 4, kcf = idx & 15;
        int f = (kcf >> 2) * 4 + (kcf & 3);
        sm[SWP + idx] = Wp[f * 64 + jj];
    }
    if (tid < 512) {                                     // biases
        int row = tid >> 6, jj = tid & 63; float v;
        if (row < 3)       v = bi1[row * 64 + jj];
        else if (row == 3) v = bhn1[jj];
        else if (row < 7)  v = bi2[(row - 4) * 64 + jj];
        else               v = bp[jj];
        sm[SBIAS + tid] = v;
    }
    if (tid < 512) sm[H1B + tid] = 0.f;                  // zero h1+h2 (contiguous 512)

    // ---------- x prologue (loader: first 32 threads of group 2) ----------
    float rx = 0.f;
    size_t xbase = 0;
    if (grp == 2 && g < 32) {
        int b = g >> 4, f = g & 15;
        int bg = blockIdx.x * 2 + b;
        xbase = (size_t)bg * T_N * 16 + f;
        sm[XBUF + 0 * 32 + b * 16 + f] = x[xbase];        // t=0
        sm[XBUF + 1 * 32 + b * 16 + f] = x[xbase + 16];   // t=1
        rx = x[xbase + 32];                               // t=2
    }
    __syncthreads();

    // xp[t=0] precompute (group 1)
    if (grp == 1) {
        u64 p0 = 0, p1 = 0;
        ulonglong2 w  = *reinterpret_cast<const ulonglong2*>(sm + SWP + j * 16 + kc4);
        ulonglong2 xa = *reinterpret_cast<const ulonglong2*>(sm + XBUF + kc4);
        ulonglong2 xc = *reinterpret_cast<const ulonglong2*>(sm + XBUF + 16 + kc4);
        ffma2(p0, w.x, xa.x); ffma2(p0, w.y, xa.y);
        ffma2(p1, w.x, xc.x); ffma2(p1, w.y, xc.y);
        float f0 = hsum2(p0), f1 = hsum2(p1);
        bool lo2 = kc < 2;
        float kx = lo2 ? f0 : f1, px = lo2 ? f1 : f0;
        kx += __shfl_xor_sync(0xffffffffu, px, 2);
        kx += __shfl_xor_sync(0xffffffffu, kx, 1);
        if (wr_) sm[XPB + be64 + j] = kx + sm[SBIAS + 448 + j];
    }
    __syncthreads();

    // ---------- pipelined recurrence ----------
    float am = -3.0e38f, as_ = 0.f, aacc = 0.f, po2 = 0.f;

#pragma unroll 1
    for (int i = 0; i <= T_N + 2; ++i) {
        if (grp == 0) {
            if (i < T_N) {
                int slot = i & 1;
                const float* hv = sm + H1B + slot * 128;
                u64 r0 = 0, z0 = 0, nh0 = 0, r1 = 0, z1 = 0, nh1 = 0, ni0 = 0, ni1 = 0;
                dot3x2(wA, wB, wC, hv, kc4, r0, z0, nh0, r1, z1, nh1);
                {   // input-side contributions (r,z merged; n-input separate)
                    const float* xb = sm + XBUF + (i & 3) * 32;
                    ulonglong2 xa = *reinterpret_cast<const ulonglong2*>(xb + kc4);
                    ulonglong2 xc = *reinterpret_cast<const ulonglong2*>(xb + 16 + kc4);
                    ulonglong2 wr = *reinterpret_cast<const ulonglong2*>(sm + SWI + j * 16 + kc4);
                    ulonglong2 wz = *reinterpret_cast<const ulonglong2*>(sm + SWI + 1024 + j * 16 + kc4);
                    ulonglong2 wn = *reinterpret_cast<const ulonglong2*>(sm + SWI + 2048 + j * 16 + kc4);
                    ffma2(r0,  wr.x, xa.x); ffma2(r0,  wr.y, xa.y);
                    ffma2(z0,  wz.x, xa.x); ffma2(z0,  wz.y, xa.y);
                    ffma2(ni0, wn.x, xa.x); ffma2(ni0, wn.y, xa.y);
                    ffma2(r1,  wr.x, xc.x); ffma2(r1,  wr.y, xc.y);
                    ffma2(z1,  wz.x, xc.x); ffma2(z1,  wz.y, xc.y);
                    ffma2(ni1, wn.x, xc.x); ffma2(ni1, wn.y, xc.y);
                }
                float fR0 = hsum2(r0), fZ0 = hsum2(z0), fNH0 = hsum2(nh0), fNI0 = hsum2(ni0);
                float fR1 = hsum2(r1), fZ1 = hsum2(z1), fNH1 = hsum2(nh1), fNI1 = hsum2(ni1);
                bool lo2 = kc < 2;
                float kR  = lo2 ? fR0  : fR1,  pR  = lo2 ? fR1  : fR0;
                float kZ  = lo2 ? fZ0  : fZ1,  pZ  = lo2 ? fZ1  : fZ0;
                float kNH = lo2 ? fNH0 : fNH1, pNH = lo2 ? fNH1 : fNH0;
                float kNI = lo2 ? fNI0 : fNI1, pNI = lo2 ? fNI1 : fNI0;
                kR  += __shfl_xor_sync(0xffffffffu, pR, 2);
                kZ  += __shfl_xor_sync(0xffffffffu, pZ, 2);
                kNH += __shfl_xor_sync(0xffffffffu, pNH, 2);
                kNI += __shfl_xor_sync(0xffffffffu, pNI, 2);
                kR  += __shfl_xor_sync(0xffffffffu, kR, 1);
                kZ  += __shfl_xor_sync(0xffffffffu, kZ, 1);
                kNH += __shfl_xor_sync(0xffffffffu, kNH, 1);
                kNI += __shfl_xor_sync(0xffffffffu, kNI, 1);
                float r  = sigf(kR + sm[SBIAS + j]);
                float z  = sigf(kZ + sm[SBIAS + 64 + j]);
                float n  = tanhfast(kNI + sm[SBIAS + 128 + j] + r * (kNH + sm[SBIAS + 192 + j]));
                float hp = sm[H1B + slot * 128 + be64 + pj];
                float hn = n + z * (hp - n);
                float xp = sm[XPB + slot * 128 + be64 + j];
                if (wr_) {
                    sm[H1B + (slot ^ 1) * 128 + be64 + pj] = hn;
                    sm[O1B + (i & 3) * 128 + be64 + pj]    = hn + 0.5f * xp;
                }
            }
        } else if (grp == 1) {
            // xi2[t=i-1] = o1 @ Wi2 + bi2 ; xp[t=i+1] = x @ Wp + bp
            u64 a0 = 0, a1 = 0, a2 = 0, c0 = 0, c1 = 0, c2 = 0, p0 = 0, p1 = 0;
            const float* ov = sm + O1B + ((i - 1) & 3) * 128;
            dot3x2(wA, wB, wC, ov, kc4, a0, a1, a2, c0, c1, c2);
            {
                const float* xb = sm + XBUF + ((i + 1) & 3) * 32;
                ulonglong2 w  = *reinterpret_cast<const ulonglong2*>(sm + SWP + j * 16 + kc4);
                ulonglong2 xa = *reinterpret_cast<const ulonglong2*>(xb + kc4);
                ulonglong2 xc = *reinterpret_cast<const ulonglong2*>(xb + 16 + kc4);
                ffma2(p0, w.x, xa.x); ffma2(p0, w.y, xa.y);
                ffma2(p1, w.x, xc.x); ffma2(p1, w.y, xc.y);
            }
            float fA0 = hsum2(a0), fA1 = hsum2(a1), fA2 = hsum2(a2), fP0 = hsum2(p0);
            float fC0 = hsum2(c0), fC1 = hsum2(c1), fC2 = hsum2(c2), fP1 = hsum2(p1);
            bool lo2 = kc < 2;
            float kR = lo2 ? fA0 : fC0, pR = lo2 ? fC0 : fA0;
            float kZ = lo2 ? fA1 : fC1, pZ = lo2 ? fC1 : fA1;
            float kN = lo2 ? fA2 : fC2, pN = lo2 ? fC2 : fA2;
            float kP = lo2 ? fP0 : fP1, pP = lo2 ? fP1 : fP0;
            kR += __shfl_xor_sync(0xffffffffu, pR, 2);
            kZ += __shfl_xor_sync(0xffffffffu, pZ, 2);
            kN += __shfl_xor_sync(0xffffffffu, pN, 2);
            kP += __shfl_xor_sync(0xffffffffu, pP, 2);
            kR += __shfl_xor_sync(0xffffffffu, kR, 1);
            kZ += __shfl_xor_sync(0xffffffffu, kZ, 1);
            kN += __shfl_xor_sync(0xffffffffu, kN, 1);
            kP += __shfl_xor_sync(0xffffffffu, kP, 1);
            float bR = sm[SBIAS + 256 + j], bZ = sm[SBIAS + 320 + j];
            float bN = sm[SBIAS + 384 + j], bP = sm[SBIAS + 448 + j];
            if (i >= 1 && i <= T_N && wr_) {
                int base = XI2B + ((i - 1) & 1) * 384 + be * 192;
                sm[base + j]       = kR + bR;
                sm[base + 64 + j]  = kZ + bZ;
                sm[base + 128 + j] = kN + bN;
            }
            if (i <= T_N - 2 && wr_)
                sm[XPB + ((i + 1) & 1) * 128 + be64 + j] = kP + bP;
        } else {
            if (i >= 3) {              // online softmax for t = i-3
                const float* sp = sm + SCB + ((i - 1) & 1) * 16 + be * 8;
                float sc = ((sp[0] + sp[1]) + (sp[2] + sp[3]))
                         + ((sp[4] + sp[5]) + (sp[6] + sp[7])) + cba;
                float nm   = fmaxf(am, sc);
                float corr = __expf(am - nm);
                float p    = __expf(sc - nm);
                as_  = as_  * corr + p;
                aacc = aacc * corr + p * po2;
                am   = nm;
            }
            if (i >= 2 && i <= T_N + 1) {   // layer-2 GRU for t = i-2
                int hs = i & 1;
                const float* hv = sm + H2B + hs * 128;
                u64 a0 = 0, a1 = 0, a2 = 0, c0 = 0, c1 = 0, c2 = 0;
                dot3x2(wA, wB, wC, hv, kc4, a0, a1, a2, c0, c1, c2);
                float fA0 = hsum2(a0), fA1 = hsum2(a1), fA2 = hsum2(a2);
                float fC0 = hsum2(c0), fC1 = hsum2(c1), fC2 = hsum2(c2);
                bool lo2 = kc < 2;
                float kR  = lo2 ? fA0 : fC0, pR  = lo2 ? fC0 : fA0;
                float kZ  = lo2 ? fA1 : fC1, pZ  = lo2 ? fC1 : fA1;
                float kNH = lo2 ? fA2 : fC2, pNH = lo2 ? fC2 : fA2;
                kR  += __shfl_xor_sync(0xffffffffu, pR, 2);
                kZ  += __shfl_xor_sync(0xffffffffu, pZ, 2);
                kNH += __shfl_xor_sync(0xffffffffu, pNH, 2);
                kR  += __shfl_xor_sync(0xffffffffu, kR, 1);
                kZ  += __shfl_xor_sync(0xffffffffu, kZ, 1);
                kNH += __shfl_xor_sync(0xffffffffu, kNH, 1);
                int xb2 = XI2B + (i & 1) * 384 + be * 192;
                float ir = sm[xb2 + j], iz = sm[xb2 + 64 + j], inn = sm[xb2 + 128 + j];
                float hp = sm[H2B + hs * 128 + be64 + pj];
                float r  = sigf(ir + kR);
                float z  = sigf(iz + kZ);
                float n  = tanhfast(inn + r * (kNH + cb0));
                float hn = n + z * (hp - n);
                float o1r = sm[O1B + ((i - 2) & 3) * 128 + be64 + pj];
                float o2  = hn + 0.5f * o1r;
                po2 = o2;
                if (wr_) sm[H2B + (hs ^ 1) * 128 + be64 + pj] = hn;
                float part = o2 * cwa;
                part += __shfl_xor_sync(0xffffffffu, part, 4);
                part += __shfl_xor_sync(0xffffffffu, part, 8);
                part += __shfl_xor_sync(0xffffffffu, part, 16);
                if (lane < 4 && wr_) sm[SCB + (i & 1) * 16 + be * 8 + wg] = part;
            }
            if (g < 32) {              // x stream
                if (i <= T_N - 3) sm[XBUF + ((i + 2) & 3) * 32 + (g >> 4) * 16 + (g & 15)] = rx;
                if (i <= T_N - 4) rx = x[xbase + (size_t)(i + 3) * 16];
            }
        }
        __syncthreads();
    }

    // ---------- attention finalize + MLP head ----------
    if (grp == 2 && wr_) sm[SATT + be64 + j] = aacc / as_;
    __syncthreads();

    if (tid < 256) {
        int b = tid >> 7, o = tid & 127;
        float acc = b1[o];
        const float* av = sm + SATT + b * 64;
#pragma unroll 8
        for (int k = 0; k < 64; ++k) acc += av[k] * W1[k * 128 + o];
        sm[SM1 + b * 128 + o] = fmaxf(acc, 0.f);
    }
    __syncthreads();
    if (tid < 128) {
        int b = tid >> 6, o = tid & 63;
        float acc = b2[o];
        const float* av = sm + SM1 + b * 128;
#pragma unroll 8
        for (int k = 0; k < 128; ++k) acc += av[k] * W2[k * 64 + o];
        sm[SM2 + b * 64 + o] = fmaxf(acc, 0.f);
    }
    __syncthreads();
    if (tid < 64) {
        int b = tid >> 5, o = tid & 31;
        float acc = b3[o];
        const float* av = sm + SM2 + b * 64;
#pragma unroll 8
        for (int k = 0; k < 64; ++k) acc += av[k] * W3[k * 32 + o];
        sm[SM3 + b * 32 + o] = fmaxf(acc, 0.f);
    }
    __syncthreads();
    if (tid < 4) {
        int b = tid >> 1, o = tid & 1;
        float acc = b4[o];
        const float* av = sm + SM3 + b * 32;
#pragma unroll
        for (int k = 0; k < 32; ++k) acc += av[k] * W4[k * 2 + o];
        out[((size_t)blockIdx.x * 2 + b) * 2 + o] = acc;
    }
}

extern "C" void kernel_launch(void* const* d_in, const int* in_sizes, int n_in,
                              void* d_out, int out_size) {
    (void)in_sizes; (void)n_in; (void)out_size;
    const float* x    = (const float*)d_in[0];
    const float* Wi1  = (const float*)d_in[1];
    const float* bi1  = (const float*)d_in[2];
    const float* Whr1 = (const float*)d_in[3];
    const float* Whz1 = (const float*)d_in[4];
    const float* Whn1 = (const float*)d_in[5];
    const float* bhn1 = (const float*)d_in[6];
    const float* Wi2  = (const float*)d_in[7];
    const float* bi2  = (const float*)d_in[8];
    const float* Whr2 = (const float*)d_in[9];
    const float* Whz2 = (const float*)d_in[10];
    const float* Whn2 = (const float*)d_in[11];
    const float* bhn2 = (const float*)d_in[12];
    const float* Wp   = (const float*)d_in[13];
    const float* bp   = (const float*)d_in[14];
    const float* Wa   = (const float*)d_in[15];
    const float* ba   = (const float*)d_in[16];
    const float* W1   = (const float*)d_in[17];
    const float* b1   = (const float*)d_in[18];
    const float* W2   = (const float*)d_in[19];
    const float* b2   = (const float*)d_in[20];
    const float* W3   = (const float*)d_in[21];
    const float* b3   = (const float*)d_in[22];
    const float* W4   = (const float*)d_in[23];
    const float* b4   = (const float*)d_in[24];
    float* out = (float*)d_out;

    solar_fused<<<128, 768>>>(x, Wi1, bi1, Whr1, Whz1, Whn1, bhn1,
                              Wi2, bi2, Whr2, Whz2, Whn2, bhn2,
                              Wp, bp, Wa, ba,
                              W1, b1, W2, b2, W3, b3, W4, b4, out);
}

// round 6
// speedup vs baseline: 1.6938x; 1.6938x over previous
#include <cuda_runtime.h>
#include <cuda_bf16.h>

typedef unsigned long long u64;

#define T_N 4096

// ---- shared layout (float word offsets) ----
#define SWI   0        // Wi1: [3 dots][128 jk][8] = 3072
#define H1B   3072     // [2 slot][2 b][36*2 padded] = 288
#define H2B   3360     // 288
#define O1B   3648     // ring [16 slot][2 b][72] = 2304
#define XBUF  5952     // [16 slot][2 b][16] = 512
#define XI2B  6464     // [8 slot][2 b][196 pad] = 3136
#define XPB   9600     // [8 slot][2 b][68 pad] = 1088
#define SCB   10688    // [2 slot][2 b][4 wg] = 16
#define SATT  10704    // [2][64] = 128
#define SM1   10832    // 256
#define SM2   11088    // 128
#define SM3   11216    // 64
#define STOT  11280

#define NBAR(id) asm volatile("bar.sync %0, %1;" :: "r"(id), "r"(128) : "memory")

__device__ __forceinline__ void ffma2(u64 &d, u64 a, u64 b) {
    asm("fma.rn.f32x2 %0, %1, %2, %0;" : "+l"(d) : "l"(a), "l"(b));
}
__device__ __forceinline__ u64 pack2(float lo, float hi) {
    u64 r; asm("mov.b64 %0, {%1, %2};" : "=l"(r) : "f"(lo), "f"(hi)); return r;
}
__device__ __forceinline__ float hsum2(u64 a) {
    float lo, hi;
    asm("mov.b64 {%0, %1}, %2;" : "=f"(lo), "=f"(hi) : "l"(a));
    return lo + hi;
}
// lane kc finalizes batch kc: keep own-batch partial, exchange partner-batch partial
__device__ __forceinline__ float xred(float b0, float b1, int kc) {
    float keep = kc ? b1 : b0;
    float send = kc ? b0 : b1;
    return keep + __shfl_xor_sync(0xffffffffu, send, 1);
}
__device__ __forceinline__ float sigf(float v)     { return __fdividef(1.f, 1.f + __expf(-v)); }
__device__ __forceinline__ float tanhfast(float v) { return 1.f - __fdividef(2.f, __expf(2.f * v) + 1.f); }

// 3 matrices x 2 batches, k-half (32) per thread, weights in registers.
// state vec layout per slot: [b][kc-half 32 + 4 pad] (stride 72 per b, 144 per slot)
__device__ __forceinline__ void dot6(const u64 (&wa)[16], const u64 (&wb)[16], const u64 (&wc)[16],
                                     const float* v, int kc36,
                                     u64 &a0, u64 &a1, u64 &a2, u64 &c0, u64 &c1, u64 &c2)
{
    const ulonglong2* h0 = reinterpret_cast<const ulonglong2*>(v + kc36);
    const ulonglong2* h1 = reinterpret_cast<const ulonglong2*>(v + 72 + kc36);
#pragma unroll
    for (int m = 0; m < 8; ++m) {
        ulonglong2 x0 = h0[m], x1 = h1[m];
        ffma2(a0, wa[2*m], x0.x); ffma2(a0, wa[2*m+1], x0.y);
        ffma2(a1, wb[2*m], x0.x); ffma2(a1, wb[2*m+1], x0.y);
        ffma2(a2, wc[2*m], x0.x); ffma2(a2, wc[2*m+1], x0.y);
        ffma2(c0, wa[2*m], x1.x); ffma2(c0, wa[2*m+1], x1.y);
        ffma2(c1, wb[2*m], x1.x); ffma2(c1, wb[2*m+1], x1.y);
        ffma2(c2, wc[2*m], x1.x); ffma2(c2, wc[2*m+1], x1.y);
    }
}

__global__ __launch_bounds__(384, 1)
void solar_fused(const float* __restrict__ x,
                 const float* __restrict__ Wi1,  const float* __restrict__ bi1,
                 const float* __restrict__ Whr1, const float* __restrict__ Whz1,
                 const float* __restrict__ Whn1, const float* __restrict__ bhn1,
                 const float* __restrict__ Wi2,  const float* __restrict__ bi2,
                 const float* __restrict__ Whr2, const float* __restrict__ Whz2,
                 const float* __restrict__ Whn2, const float* __restrict__ bhn2,
                 const float* __restrict__ Wp,   const float* __restrict__ bp,
                 const float* __restrict__ Wa,   const float* __restrict__ ba,
                 const float* __restrict__ W1,   const float* __restrict__ b1,
                 const float* __restrict__ W2,   const float* __restrict__ b2,
                 const float* __restrict__ W3,   const float* __restrict__ b3,
                 const float* __restrict__ W4,   const float* __restrict__ b4,
                 float* __restrict__ out)
{
    __shared__ __align__(16) float sm[STOT];

    const int tid  = threadIdx.x;
    const int grp  = tid >> 7;       // 0: L1-GRU, 1: Wi2+xp+loader, 2: L2-GRU+attn
    const int g    = tid & 127;
    const int j    = g >> 1;         // 0..63
    const int kc   = g & 1;          // k-half / finalized batch
    const int kc8  = kc * 8;
    const int kc36 = kc * 36;
    const int lane = tid & 31;
    const int wg   = g >> 5;         // warp within group 0..3
    const int widx = kc * 72 + (j >> 5) * 36 + (j & 31); // scalar slot (batch kc, elem j)

    // ---------- register-resident weights ----------
    u64 wA[16], wB[16], wC[16], wD[4];
    float cb0 = 0.f, cb1 = 0.f, cb2 = 0.f, cb3 = 0.f, cwa = 0.f, cba = 0.f;
    if (grp == 0) {
#pragma unroll
        for (int m = 0; m < 16; ++m) {
            int k = kc * 32 + 2 * m;
            wA[m] = pack2(Whr1[k*64 + j], Whr1[(k+1)*64 + j]);
            wB[m] = pack2(Whz1[k*64 + j], Whz1[(k+1)*64 + j]);
            wC[m] = pack2(Whn1[k*64 + j], Whn1[(k+1)*64 + j]);
        }
        cb0 = bi1[j]; cb1 = bi1[64 + j]; cb2 = bi1[128 + j]; cb3 = bhn1[j];
    } else if (grp == 1) {
#pragma unroll
        for (int m = 0; m < 16; ++m) {
            int k = kc * 32 + 2 * m;
            wA[m] = pack2(Wi2[k*192 + j],       Wi2[(k+1)*192 + j]);
            wB[m] = pack2(Wi2[k*192 + 64 + j],  Wi2[(k+1)*192 + 64 + j]);
            wC[m] = pack2(Wi2[k*192 + 128 + j], Wi2[(k+1)*192 + 128 + j]);
        }
#pragma unroll
        for (int m = 0; m < 4; ++m) {
            int f = kc * 8 + 2 * m;
            wD[m] = pack2(Wp[f*64 + j], Wp[(f+1)*64 + j]);
        }
        cb0 = bi2[j]; cb1 = bi2[64 + j]; cb2 = bi2[128 + j]; cb3 = bp[j];
    } else {
#pragma unroll
        for (int m = 0; m < 16; ++m) {
            int k = kc * 32 + 2 * m;
            wA[m] = pack2(Whr2[k*64 + j], Whr2[(k+1)*64 + j]);
            wB[m] = pack2(Whz2[k*64 + j], Whz2[(k+1)*64 + j]);
            wC[m] = pack2(Whn2[k*64 + j], Whn2[(k+1)*64 + j]);
        }
        cb0 = bhn2[j]; cwa = Wa[j]; cba = ba[0];
    }

    // ---------- shared setup: Wi1 + zero state ----------
    for (int idx = tid; idx < 3072; idx += 384) {      // [dot][j*2+kc][8]
        int d = idx >> 10, rem = idx & 1023;
        int jk = rem >> 3, fl = rem & 7;
        sm[SWI + idx] = Wi1[((jk & 1) * 8 + fl) * 192 + d * 64 + (jk >> 1)];
    }
    for (int idx = tid; idx < 576; idx += 384) sm[H1B + idx] = 0.f;   // h1+h2 both slots

    // ---------- x prologue (loader lanes: first 32 threads of group 1) ----------
    float rx = 0.f;
    size_t xbase = 0;
    if (grp == 1 && g < 32) {
        int b = g >> 4, f = g & 15;
        int bg = blockIdx.x * 2 + b;
        xbase = (size_t)bg * T_N * 16 + f;
#pragma unroll
        for (int t = 0; t < 5; ++t) sm[XBUF + t * 32 + b * 16 + f] = x[xbase + (size_t)t * 16];
        rx = x[xbase + 80];                            // t=5
    }
    __syncthreads();

    // xp[t=0..3] prologue (group 1)
    if (grp == 1) {
#pragma unroll
        for (int tt = 0; tt < 4; ++tt) {
            const float* xb = sm + XBUF + tt * 32;
            u64 p0 = 0, p1 = 0;
            const ulonglong2* xa = reinterpret_cast<const ulonglong2*>(xb + kc8);
            const ulonglong2* xc = reinterpret_cast<const ulonglong2*>(xb + 16 + kc8);
#pragma unroll
            for (int m = 0; m < 2; ++m) {
                ulonglong2 a = xa[m], c = xc[m];
                ffma2(p0, wD[2*m], a.x); ffma2(p0, wD[2*m+1], a.y);
                ffma2(p1, wD[2*m], c.x); ffma2(p1, wD[2*m+1], c.y);
            }
            sm[XPB + tt * 136 + kc * 68 + j] = xred(hsum2(p0), hsum2(p1), kc) + cb3;
        }
    }
    __syncthreads();

    // ---------- recurrence: g0 @ t=i, g1 @ t=i-4 (xi2) / t=i+4 (xp), g2 @ t=i-8 ----------
    float am = -3.0e38f, as_ = 0.f, aacc = 0.f, po2 = 0.f;

#pragma unroll 1
    for (int i = 0; i <= T_N + 8; ++i) {
        if (grp == 0) {
            if (i < T_N) {
                int slot = i & 1;
                const float* hv = sm + H1B + slot * 144;
                u64 r0=0, z0=0, nh0=0, r1=0, z1=0, nh1=0, ni0=0, ni1=0;
                dot6(wA, wB, wC, hv, kc36, r0, z0, nh0, r1, z1, nh1);
                {   // input-side over x_t (8 per kc-half)
                    const float* xb = sm + XBUF + (i & 15) * 32;
                    const ulonglong2* x0p = reinterpret_cast<const ulonglong2*>(xb + kc8);
                    const ulonglong2* x1p = reinterpret_cast<const ulonglong2*>(xb + 16 + kc8);
                    const ulonglong2* wiR = reinterpret_cast<const ulonglong2*>(sm + SWI + (j*2+kc)*8);
                    const ulonglong2* wiZ = reinterpret_cast<const ulonglong2*>(sm + SWI + 1024 + (j*2+kc)*8);
                    const ulonglong2* wiN = reinterpret_cast<const ulonglong2*>(sm + SWI + 2048 + (j*2+kc)*8);
#pragma unroll
                    for (int m = 0; m < 2; ++m) {
                        ulonglong2 xa = x0p[m], xc = x1p[m];
                        ulonglong2 wr = wiR[m], wz = wiZ[m], wn = wiN[m];
                        ffma2(r0,  wr.x, xa.x); ffma2(r0,  wr.y, xa.y);
                        ffma2(z0,  wz.x, xa.x); ffma2(z0,  wz.y, xa.y);
                        ffma2(ni0, wn.x, xa.x); ffma2(ni0, wn.y, xa.y);
                        ffma2(r1,  wr.x, xc.x); ffma2(r1,  wr.y, xc.y);
                        ffma2(z1,  wz.x, xc.x); ffma2(z1,  wz.y, xc.y);
                        ffma2(ni1, wn.x, xc.x); ffma2(ni1, wn.y, xc.y);
                    }
                }
                float fR  = xred(hsum2(r0),  hsum2(r1),  kc);
                float fZ  = xred(hsum2(z0),  hsum2(z1),  kc);
                float fNH = xred(hsum2(nh0), hsum2(nh1), kc);
                float fNI = xred(hsum2(ni0), hsum2(ni1), kc);
                float r  = sigf(fR + cb0);
                float z  = sigf(fZ + cb1);
                float n  = tanhfast(fNI + cb2 + r * (fNH + cb3));
                float hp = sm[H1B + slot * 144 + widx];
                float hn = n + z * (hp - n);
                float xp = sm[XPB + (i & 7) * 136 + kc * 68 + j];
                sm[H1B + (slot ^ 1) * 144 + widx] = hn;
                sm[O1B + (i & 15) * 144 + widx]   = hn + 0.5f * xp;
            }
            NBAR(1);
        } else if (grp == 1) {
            if (i >= 4 && i <= T_N + 3) {     // xi2[t=i-4] = o1[i-4] @ Wi2 + bi2
                const float* ov = sm + O1B + ((i + 12) & 15) * 144;
                u64 a0=0, a1=0, a2=0, c0=0, c1=0, c2=0;
                dot6(wA, wB, wC, ov, kc36, a0, a1, a2, c0, c1, c2);
                float fR = xred(hsum2(a0), hsum2(c0), kc) + cb0;
                float fZ = xred(hsum2(a1), hsum2(c1), kc) + cb1;
                float fN = xred(hsum2(a2), hsum2(c2), kc) + cb2;
                int base = XI2B + ((i + 4) & 7) * 392 + kc * 196;
                sm[base + j]       = fR;
                sm[base + 64 + j]  = fZ;
                sm[base + 128 + j] = fN;
            }
            if (i <= T_N - 5) {               // xp[t=i+4]
                const float* xb = sm + XBUF + ((i + 4) & 15) * 32;
                u64 p0 = 0, p1 = 0;
                const ulonglong2* xa = reinterpret_cast<const ulonglong2*>(xb + kc8);
                const ulonglong2* xc = reinterpret_cast<const ulonglong2*>(xb + 16 + kc8);
#pragma unroll
                for (int m = 0; m < 2; ++m) {
                    ulonglong2 a = xa[m], c = xc[m];
                    ffma2(p0, wD[2*m], a.x); ffma2(p0, wD[2*m+1], a.y);
                    ffma2(p1, wD[2*m], c.x); ffma2(p1, wD[2*m+1], c.y);
                }
                sm[XPB + ((i + 4) & 7) * 136 + kc * 68 + j] = xred(hsum2(p0), hsum2(p1), kc) + cb3;
            }
            if (g < 32) {                     // x stream: store t=i+5, prefetch t=i+6
                if (i <= T_N - 6) sm[XBUF + ((i + 5) & 15) * 32 + (g >> 4) * 16 + (g & 15)] = rx;
                if (i <= T_N - 7) rx = x[xbase + (size_t)(i + 6) * 16];
            }
            NBAR(2);
        } else {
            if (i >= 9) {                     // online softmax for t = i-9
                const float* sp = sm + SCB + ((i - 1) & 1) * 8 + kc * 4;
                float sc   = (sp[0] + sp[1]) + (sp[2] + sp[3]) + cba;
                float nm   = fmaxf(am, sc);
                float corr = __expf(am - nm);
                float p    = __expf(sc - nm);
                as_  = as_  * corr + p;
                aacc = aacc * corr + p * po2;
                am   = nm;
            }
            if (i >= 8 && i <= T_N + 7) {     // layer-2 GRU for t = i-8
                int hs = i & 1;
                const float* hv = sm + H2B + hs * 144;
                u64 a0=0, a1=0, a2=0, c0=0, c1=0, c2=0;
                dot6(wA, wB, wC, hv, kc36, a0, a1, a2, c0, c1, c2);
                float fR  = xred(hsum2(a0), hsum2(c0), kc);
                float fZ  = xred(hsum2(a1), hsum2(c1), kc);
                float fNH = xred(hsum2(a2), hsum2(c2), kc);
                int xb2 = XI2B + (i & 7) * 392 + kc * 196;
                float ir = sm[xb2 + j], iz = sm[xb2 + 64 + j], inn = sm[xb2 + 128 + j];
                float hp = sm[H2B + hs * 144 + widx];
                float r  = sigf(ir + fR);
                float z  = sigf(iz + fZ);
                float n  = tanhfast(inn + r * (fNH + cb0));
                float hn = n + z * (hp - n);
                float o1r = sm[O1B + ((i + 8) & 15) * 144 + widx];
                float o2  = hn + 0.5f * o1r;
                po2 = o2;
                sm[H2B + (hs ^ 1) * 144 + widx] = hn;
                float part = o2 * cwa;        // score partial for batch kc
                part += __shfl_xor_sync(0xffffffffu, part, 2);
                part += __shfl_xor_sync(0xffffffffu, part, 4);
                part += __shfl_xor_sync(0xffffffffu, part, 8);
                part += __shfl_xor_sync(0xffffffffu, part, 16);
                if (lane < 2) sm[SCB + (i & 1) * 8 + kc * 4 + wg] = part;
            }
            NBAR(3);
        }
        if ((i & 3) == 3) __syncthreads();    // cross-group deps are all skew >= 4
    }
    __syncthreads();

    // ---------- attention finalize + MLP head ----------
    if (grp == 2) sm[SATT + kc * 64 + j] = aacc / as_;
    __syncthreads();

    if (tid < 256) {
        int b = tid >> 7, o = tid & 127;
        float acc = b1[o];
        const float* av = sm + SATT + b * 64;
#pragma unroll 8
        for (int k = 0; k < 64; ++k) acc += av[k] * W1[k * 128 + o];
        sm[SM1 + b * 128 + o] = fmaxf(acc, 0.f);
    }
    __syncthreads();
    if (tid < 128) {
        int b = tid >> 6, o = tid & 63;
        float acc = b2[o];
        const float* av = sm + SM1 + b * 128;
#pragma unroll 8
        for (int k = 0; k < 128; ++k) acc += av[k] * W2[k * 64 + o];
        sm[SM2 + b * 64 + o] = fmaxf(acc, 0.f);
    }
    __syncthreads();
    if (tid < 64) {
        int b = tid >> 5, o = tid & 31;
        float acc = b3[o];
        const float* av = sm + SM2 + b * 64;
#pragma unroll 8
        for (int k = 0; k < 64; ++k) acc += av[k] * W3[k * 32 + o];
        sm[SM3 + b * 32 + o] = fmaxf(acc, 0.f);
    }
    __syncthreads();
    if (tid < 4) {
        int b = tid >> 1, o = tid & 1;
        float acc = b4[o];
        const float* av = sm + SM3 + b * 32;
#pragma unroll
        for (int k = 0; k < 32; ++k) acc += av[k] * W4[k * 2 + o];
        out[((size_t)blockIdx.x * 2 + b) * 2 + o] = acc;
    }
}

extern "C" void kernel_launch(void* const* d_in, const int* in_sizes, int n_in,
                              void* d_out, int out_size) {
    (void)in_sizes; (void)n_in; (void)out_size;
    const float* x    = (const float*)d_in[0];
    const float* Wi1  = (const float*)d_in[1];
    const float* bi1  = (const float*)d_in[2];
    const float* Whr1 = (const float*)d_in[3];
    const float* Whz1 = (const float*)d_in[4];
    const float* Whn1 = (const float*)d_in[5];
    const float* bhn1 = (const float*)d_in[6];
    const float* Wi2  = (const float*)d_in[7];
    const float* bi2  = (const float*)d_in[8];
    const float* Whr2 = (const float*)d_in[9];
    const float* Whz2 = (const float*)d_in[10];
    const float* Whn2 = (const float*)d_in[11];
    const float* bhn2 = (const float*)d_in[12];
    const float* Wp   = (const float*)d_in[13];
    const float* bp   = (const float*)d_in[14];
    const float* Wa   = (const float*)d_in[15];
    const float* ba   = (const float*)d_in[16];
    const float* W1   = (const float*)d_in[17];
    const float* b1   = (const float*)d_in[18];
    const float* W2   = (const float*)d_in[19];
    const float* b2   = (const float*)d_in[20];
    const float* W3   = (const float*)d_in[21];
    const float* b3   = (const float*)d_in[22];
    const float* W4   = (const float*)d_in[23];
    const float* b4   = (const float*)d_in[24];
    float* out = (float*)d_out;

    solar_fused<<<128, 384>>>(x, Wi1, bi1, Whr1, Whz1, Whn1, bhn1,
                              Wi2, bi2, Whr2, Whz2, Whn2, bhn2,
                              Wp, bp, Wa, ba,
                              W1, b1, W2, b2, W3, b3, W4, b4, out);
}